// round 15
// baseline (speedup 1.0000x reference)
#include <cuda_runtime.h>
#include <cuda_bf16.h>
#include <cuda_fp16.h>
#include <math.h>
#include <float.h>
#include <stdint.h>

#define Bb   4
#define Nn   1024
#define DIMm 1024
#define Hh   16
#define DHh  64
#define Mm   16
#define NJ   1040          // M + N
#define PJ   1088          // padded kv length (multiple of 64)
#define ROWS 4096          // B*N
#define QK_SCALE 10.0f

// ===================== scratch =============================================
__device__ float g_Qraw[(size_t)ROWS * DIMm];
__device__ float g_Kraw[(size_t)ROWS * DIMm];
__device__ float g_Vraw[(size_t)ROWS * DIMm];
__device__ float g_vgraw[(size_t)ROWS * DIMm];
__device__ float g_hgraw[(size_t)ROWS * Hh];
__device__ float g_dots[(size_t)64 * Nn * NJ];
__device__ float g_Ohd[(size_t)64 * Nn * DHh];
__device__ float g_Whgt[16 * 1024];
__device__ __nv_bfloat16 g_Qh[(size_t)64 * Nn * DHh];
__device__ __nv_bfloat16 g_Ql[(size_t)64 * Nn * DHh];
__device__ __nv_bfloat16 g_Kh[(size_t)64 * PJ * DHh];   // pad rows stay zero
__device__ __nv_bfloat16 g_Kl[(size_t)64 * PJ * DHh];
__device__ __half g_Vh16[(size_t)64 * PJ * DHh];        // pad rows stay zero
__device__ __half g_Vl16[(size_t)64 * PJ * DHh];
__device__ __half g_P16[(size_t)64 * Nn * PJ];
__device__ __nv_bfloat16 g_Ahi[(size_t)ROWS * DIMm];    // x bf16 hi/lo (Q,K path)
__device__ __nv_bfloat16 g_Alo[(size_t)ROWS * DIMm];
__device__ __half g_xf[(size_t)ROWS * DIMm];            // x fp16 (V,vgate path)
__device__ __half g_of[(size_t)ROWS * DIMm];            // gated out fp16 (Wo path)
__device__ __nv_bfloat16 g_Wthi[(size_t)2 * DIMm * DIMm];  // Wq, Wk (bf16 hi/lo)
__device__ __nv_bfloat16 g_Wtlo[(size_t)2 * DIMm * DIMm];
__device__ __half g_Wfhi[(size_t)3 * DIMm * DIMm];         // Wv, Wvg, Wo (fp16 hi/lo)
__device__ __half g_Wflo[(size_t)3 * DIMm * DIMm];

// ===================== PTX helpers (base ISA only) =========================
__device__ __forceinline__ uint32_t smem_u32(const void* p) {
    uint32_t a;
    asm("{ .reg .u64 tmp; cvta.to.shared.u64 tmp, %1; cvt.u32.u64 %0, tmp; }"
        : "=r"(a) : "l"(p));
    return a;
}
__device__ __forceinline__ void cp_async16(uint32_t s, const void* g) {
    asm volatile("cp.async.cg.shared.global [%0], [%1], 16;" :: "r"(s), "l"(g));
}
__device__ __forceinline__ void cp_commit() {
    asm volatile("cp.async.commit_group;" ::: "memory");
}
__device__ __forceinline__ void cp_wait1() {
    asm volatile("cp.async.wait_group 1;" ::: "memory");
}
__device__ __forceinline__ void cp_wait0() {
    asm volatile("cp.async.wait_group 0;" ::: "memory");
}
__device__ __forceinline__ void ldsm_x4(uint32_t* r, uint32_t addr) {
    asm volatile("ldmatrix.sync.aligned.m8n8.x4.shared.b16 {%0,%1,%2,%3}, [%4];"
                 : "=r"(r[0]), "=r"(r[1]), "=r"(r[2]), "=r"(r[3]) : "r"(addr));
}
__device__ __forceinline__ void ldsm_x4_t(uint32_t* r, uint32_t addr) {
    asm volatile("ldmatrix.sync.aligned.m8n8.x4.trans.shared.b16 {%0,%1,%2,%3}, [%4];"
                 : "=r"(r[0]), "=r"(r[1]), "=r"(r[2]), "=r"(r[3]) : "r"(addr));
}
__device__ __forceinline__ void mma16816(float* d, const uint32_t* a, const uint32_t* b) {
    asm volatile(
        "mma.sync.aligned.m16n8k16.row.col.f32.bf16.bf16.f32 "
        "{%0,%1,%2,%3}, {%4,%5,%6,%7}, {%8,%9}, {%0,%1,%2,%3};"
        : "+f"(d[0]), "+f"(d[1]), "+f"(d[2]), "+f"(d[3])
        : "r"(a[0]), "r"(a[1]), "r"(a[2]), "r"(a[3]), "r"(b[0]), "r"(b[1]));
}
__device__ __forceinline__ void mma16816h(float* d, const uint32_t* a, const uint32_t* b) {
    asm volatile(
        "mma.sync.aligned.m16n8k16.row.col.f32.f16.f16.f32 "
        "{%0,%1,%2,%3}, {%4,%5,%6,%7}, {%8,%9}, {%0,%1,%2,%3};"
        : "+f"(d[0]), "+f"(d[1]), "+f"(d[2]), "+f"(d[3])
        : "r"(a[0]), "r"(a[1]), "r"(a[2]), "r"(a[3]), "r"(b[0]), "r"(b[1]));
}

// ===================== convert kernels =====================================
__global__ void conv_x(const float* __restrict__ src) {
    int i = blockIdx.x * 256 + threadIdx.x;
    float4 v = ((const float4*)src)[i];
    float f[4] = {v.x, v.y, v.z, v.w};
    __nv_bfloat16 h[4], l[4];
    __half x16[4];
#pragma unroll
    for (int k = 0; k < 4; k++) {
        h[k] = __float2bfloat16(f[k]);
        l[k] = __float2bfloat16(f[k] - __bfloat162float(h[k]));
        x16[k] = __float2half(f[k]);
    }
    __nv_bfloat162 p0, p1, q0, q1;
    p0.x = h[0]; p0.y = h[1]; p1.x = h[2]; p1.y = h[3];
    q0.x = l[0]; q0.y = l[1]; q1.x = l[2]; q1.y = l[3];
    ((__nv_bfloat162*)g_Ahi)[i * 2] = p0; ((__nv_bfloat162*)g_Ahi)[i * 2 + 1] = p1;
    ((__nv_bfloat162*)g_Alo)[i * 2] = q0; ((__nv_bfloat162*)g_Alo)[i * 2 + 1] = q1;
    __half2 r0, r1; r0.x = x16[0]; r0.y = x16[1]; r1.x = x16[2]; r1.y = x16[3];
    ((__half2*)g_xf)[i * 2] = r0; ((__half2*)g_xf)[i * 2 + 1] = r1;
}

__global__ void conv_w_t(const float* __restrict__ W0, const float* __restrict__ W1,
                         const float* __restrict__ W2, const float* __restrict__ W3,
                         const float* __restrict__ W4) {
    const float* Ws[5] = {W0, W1, W2, W3, W4};
    int z = blockIdx.z;
    const float* W = Ws[z];
    __shared__ float tile[32][33];
    int k0 = blockIdx.y * 32, n0 = blockIdx.x * 32;
    int c = threadIdx.x & 31, r8 = threadIdx.x >> 5;
#pragma unroll
    for (int i = 0; i < 4; i++) {
        int r = r8 + i * 8;
        tile[r][c] = W[(size_t)(k0 + r) * DIMm + n0 + c];
    }
    __syncthreads();
    if (z < 2) {
        __nv_bfloat16* hi = g_Wthi + (size_t)z * DIMm * DIMm;
        __nv_bfloat16* lo = g_Wtlo + (size_t)z * DIMm * DIMm;
#pragma unroll
        for (int i = 0; i < 4; i++) {
            int r = r8 + i * 8;
            float v = tile[c][r];
            __nv_bfloat16 h = __float2bfloat16(v);
            hi[(size_t)(n0 + r) * DIMm + k0 + c] = h;
            lo[(size_t)(n0 + r) * DIMm + k0 + c] = __float2bfloat16(v - __bfloat162float(h));
        }
    } else {
        __half* hi = g_Wfhi + (size_t)(z - 2) * DIMm * DIMm;
        __half* lo = g_Wflo + (size_t)(z - 2) * DIMm * DIMm;
#pragma unroll
        for (int i = 0; i < 4; i++) {
            int r = r8 + i * 8;
            float v = tile[c][r];
            __half h = __float2half(v);
            hi[(size_t)(n0 + r) * DIMm + k0 + c] = h;
            lo[(size_t)(n0 + r) * DIMm + k0 + c] = __float2half(v - __half2float(h));
        }
    }
}

__global__ void hg_t(const float* __restrict__ W) {
    int idx = blockIdx.x * 256 + threadIdx.x;   // 16384
    int h = idx >> 10, k = idx & 1023;
    g_Whgt[idx] = W[k * 16 + h];
}

// ========== bf16 hi/lo 3-pass GEMM (Q,K), CTA tile 128x128 =================
__global__ __launch_bounds__(256)
void mma_gemm_bf(const __nv_bfloat16* __restrict__ Ahi, const __nv_bfloat16* __restrict__ Alo,
                 float* __restrict__ C0, float* __restrict__ C1) {
    extern __shared__ __align__(1024) char smem[];
    uint32_t sbase = smem_u32(smem);
    int z = blockIdx.z;
    const __nv_bfloat16* Bh = g_Wthi + (size_t)z * DIMm * DIMm;
    const __nv_bfloat16* Bl = g_Wtlo + (size_t)z * DIMm * DIMm;
    float* C = (z == 0) ? C0 : C1;

    int t = threadIdx.x;
    int lane = t & 31, w = t >> 5;
    int wm = w >> 2, wn = w & 3;
    int i0 = blockIdx.y * 128, n0 = blockIdx.x * 128;

    float acc[4][4][4] = {};

    int a_rl = ((lane >> 3) & 1) * 8 + (lane & 7);
    int a_ch = lane >> 4;
    int b_nl = (lane & 7) + ((lane >> 4) & 1) * 8;
    int b_ch = (lane >> 3) & 1;

    auto issue_load = [&](int ks) {
        uint32_t stage = sbase + (uint32_t)(ks & 1) * 32768u;
        int k0 = ks * 32;
#pragma unroll
        for (int i = 0; i < 8; i++) {
            int tile = i >> 1;
            int ci = ((i & 1) << 8) + t;
            int r = ci >> 2, c = ci & 3;
            const __nv_bfloat16* src = (tile == 0) ? Ahi : (tile == 1) ? Alo
                                     : (tile == 2) ? Bh : Bl;
            int rb = (tile < 2) ? i0 : n0;
            const __nv_bfloat16* g = src + (size_t)(rb + r) * DIMm + k0 + c * 8;
            uint32_t s = stage + (uint32_t)(tile * 8192 + r * 64 +
                          (((c ^ ((r >> 1) & 3))) << 4));
            cp_async16(s, g);
        }
        cp_commit();
    };

    issue_load(0);
    const int NS = DIMm / 32;
    for (int ks = 0; ks < NS; ks++) {
        if (ks + 1 < NS) issue_load(ks + 1);
        if (ks + 1 < NS) cp_wait1(); else cp_wait0();
        __syncthreads();
        uint32_t sb = sbase + (uint32_t)(ks & 1) * 32768u;
        uint32_t aH = sb, aL = sb + 8192, bH = sb + 16384, bL = sb + 24576;
#pragma unroll
        for (int kk = 0; kk < 2; kk++) {
            int c0 = kk * 2;
            uint32_t fBh[2][4], fBl[2][4], fA[4][4];
#pragma unroll
            for (int ng = 0; ng < 2; ng++) {
                int n = wn * 32 + ng * 16 + b_nl;
                int c = c0 + b_ch;
                uint32_t off = (uint32_t)(n * 64 + ((c ^ ((n >> 1) & 3)) << 4));
                ldsm_x4(fBh[ng], bH + off);
                ldsm_x4(fBl[ng], bL + off);
            }
#pragma unroll
            for (int mt = 0; mt < 4; mt++) {
                int r = wm * 64 + mt * 16 + a_rl;
                int c = c0 + a_ch;
                uint32_t off = (uint32_t)(r * 64 + ((c ^ ((r >> 1) & 3)) << 4));
                ldsm_x4(fA[mt], aH + off);
            }
#pragma unroll
            for (int mt = 0; mt < 4; mt++)
#pragma unroll
                for (int nt = 0; nt < 4; nt++) {
                    mma16816(acc[mt][nt], fA[mt], &fBh[nt >> 1][(nt & 1) * 2]);
                    mma16816(acc[mt][nt], fA[mt], &fBl[nt >> 1][(nt & 1) * 2]);
                }
#pragma unroll
            for (int mt = 0; mt < 4; mt++) {
                int r = wm * 64 + mt * 16 + a_rl;
                int c = c0 + a_ch;
                uint32_t off = (uint32_t)(r * 64 + ((c ^ ((r >> 1) & 3)) << 4));
                ldsm_x4(fA[mt], aL + off);
            }
#pragma unroll
            for (int mt = 0; mt < 4; mt++)
#pragma unroll
                for (int nt = 0; nt < 4; nt++)
                    mma16816(acc[mt][nt], fA[mt], &fBh[nt >> 1][(nt & 1) * 2]);
        }
        __syncthreads();
    }

    int row0 = i0 + wm * 64 + (lane >> 2);
    int col0 = n0 + wn * 32 + (lane & 3) * 2;
#pragma unroll
    for (int mt = 0; mt < 4; mt++)
#pragma unroll
        for (int nt = 0; nt < 4; nt++) {
            int r = row0 + mt * 16, cc = col0 + nt * 8;
            float2 v0 = {acc[mt][nt][0], acc[mt][nt][1]};
            float2 v1 = {acc[mt][nt][2], acc[mt][nt][3]};
            *(float2*)&C[(size_t)r * DIMm + cc] = v0;
            *(float2*)&C[(size_t)(r + 8) * DIMm + cc] = v1;
        }
}

// ========== fp16 GEMM (V: 2-pass; vgate: 1-pass; Wo: 2-pass) ===============
__global__ __launch_bounds__(256)
void mma_gemm_f16(const __half* __restrict__ Af, int wbase,
                  float* __restrict__ C0, float* __restrict__ C1) {
    extern __shared__ __align__(1024) char smem[];
    uint32_t sbase = smem_u32(smem);
    int z = blockIdx.z;
    int widx = wbase + z;
    int npass = (widx == 1) ? 1 : 2;
    const __half* Bh = g_Wfhi + (size_t)widx * DIMm * DIMm;
    const __half* Bl = g_Wflo + (size_t)widx * DIMm * DIMm;
    float* C = (z == 0) ? C0 : C1;

    int t = threadIdx.x;
    int lane = t & 31, w = t >> 5;
    int wm = w >> 2, wn = w & 3;
    int i0 = blockIdx.y * 128, n0 = blockIdx.x * 128;

    float acc[4][4][4] = {};

    int a_rl = ((lane >> 3) & 1) * 8 + (lane & 7);
    int a_ch = lane >> 4;
    int b_nl = (lane & 7) + ((lane >> 4) & 1) * 8;
    int b_ch = (lane >> 3) & 1;

    auto issue_load = [&](int ks) {
        uint32_t stage = sbase + (uint32_t)(ks & 1) * 24576u;
        int k0 = ks * 32;
#pragma unroll
        for (int i = 0; i < 6; i++) {
            int ci = i * 256 + t;               // 0..1535
            int tile = ci >> 9;                 // 0: A, 1: Bh, 2: Bl
            if (tile == 2 && npass == 1) continue;
            int r = (ci & 511) >> 2, c = ci & 3;
            const __half* g = (tile == 0) ? Af + (size_t)(i0 + r) * DIMm + k0 + c * 8
                            : (tile == 1) ? Bh + (size_t)(n0 + r) * DIMm + k0 + c * 8
                                          : Bl + (size_t)(n0 + r) * DIMm + k0 + c * 8;
            uint32_t s = stage + (uint32_t)(tile * 8192 + r * 64 +
                          (((c ^ ((r >> 1) & 3))) << 4));
            cp_async16(s, g);
        }
        cp_commit();
    };

    issue_load(0);
    const int NS = DIMm / 32;
    for (int ks = 0; ks < NS; ks++) {
        if (ks + 1 < NS) issue_load(ks + 1);
        if (ks + 1 < NS) cp_wait1(); else cp_wait0();
        __syncthreads();
        uint32_t sb = sbase + (uint32_t)(ks & 1) * 24576u;
        uint32_t aF = sb, bH = sb + 8192, bL = sb + 16384;
#pragma unroll
        for (int kk = 0; kk < 2; kk++) {
            int c0 = kk * 2;
            uint32_t fB[2][4], fA[4][4];
#pragma unroll
            for (int ng = 0; ng < 2; ng++) {
                int n = wn * 32 + ng * 16 + b_nl;
                int c = c0 + b_ch;
                ldsm_x4(fB[ng], bH + (uint32_t)(n * 64 + ((c ^ ((n >> 1) & 3)) << 4)));
            }
#pragma unroll
            for (int mt = 0; mt < 4; mt++) {
                int r = wm * 64 + mt * 16 + a_rl;
                int c = c0 + a_ch;
                ldsm_x4(fA[mt], aF + (uint32_t)(r * 64 + ((c ^ ((r >> 1) & 3)) << 4)));
            }
#pragma unroll
            for (int mt = 0; mt < 4; mt++)
#pragma unroll
                for (int nt = 0; nt < 4; nt++)
                    mma16816h(acc[mt][nt], fA[mt], &fB[nt >> 1][(nt & 1) * 2]);
            if (npass == 2) {
#pragma unroll
                for (int ng = 0; ng < 2; ng++) {
                    int n = wn * 32 + ng * 16 + b_nl;
                    int c = c0 + b_ch;
                    ldsm_x4(fB[ng], bL + (uint32_t)(n * 64 + ((c ^ ((n >> 1) & 3)) << 4)));
                }
#pragma unroll
                for (int mt = 0; mt < 4; mt++)
#pragma unroll
                    for (int nt = 0; nt < 4; nt++)
                        mma16816h(acc[mt][nt], fA[mt], &fB[nt >> 1][(nt & 1) * 2]);
            }
        }
        __syncthreads();
    }

    int row0 = i0 + wm * 64 + (lane >> 2);
    int col0 = n0 + wn * 32 + (lane & 3) * 2;
#pragma unroll
    for (int mt = 0; mt < 4; mt++)
#pragma unroll
        for (int nt = 0; nt < 4; nt++) {
            int r = row0 + mt * 16, cc = col0 + nt * 8;
            float2 v0 = {acc[mt][nt][0], acc[mt][nt][1]};
            float2 v1 = {acc[mt][nt][2], acc[mt][nt][3]};
            *(float2*)&C[(size_t)r * DIMm + cc] = v0;
            *(float2*)&C[(size_t)(r + 8) * DIMm + cc] = v1;
        }
}

// ---------------- head-gate: warp per row ----------------------------------
__global__ __launch_bounds__(128) void hgate_warp(const float* __restrict__ x) {
    int w = blockIdx.x * 4 + (threadIdx.x >> 5);
    int l = threadIdx.x & 31;
    float acc[16] = {};
    const float* xr = x + (size_t)w * 1024;
#pragma unroll
    for (int i = 0; i < 8; i++) {
        float4 xv = *(const float4*)&xr[i * 128 + l * 4];
#pragma unroll
        for (int h = 0; h < 16; h++) {
            float4 wv = *(const float4*)&g_Whgt[h * 1024 + i * 128 + l * 4];
            acc[h] += xv.x * wv.x + xv.y * wv.y + xv.z * wv.z + xv.w * wv.w;
        }
    }
#pragma unroll
    for (int h = 0; h < 16; h++)
#pragma unroll
        for (int o = 16; o > 0; o >>= 1) acc[h] += __shfl_xor_sync(~0u, acc[h], o);
    if (l == 0) {
#pragma unroll
        for (int h = 0; h < 16; h++) g_hgraw[(size_t)w * 16 + h] = acc[h];
    }
}

// ---------------- l2norm + scale + rope -> split layouts -------------------
__device__ __forceinline__ void wr_hl(__nv_bfloat16* H, __nv_bfloat16* L,
                                      size_t rowoff, int lane, float2 v) {
    __nv_bfloat16 hx = __float2bfloat16(v.x), hy = __float2bfloat16(v.y);
    __nv_bfloat162 hh; hh.x = hx; hh.y = hy;
    __nv_bfloat162 ll;
    ll.x = __float2bfloat16(v.x - __bfloat162float(hx));
    ll.y = __float2bfloat16(v.y - __bfloat162float(hy));
    ((__nv_bfloat162*)(H + rowoff))[lane] = hh;
    ((__nv_bfloat162*)(L + rowoff))[lane] = ll;
}
__device__ __forceinline__ void wr_hl16(__half* H, __half* L,
                                        size_t rowoff, int lane, float2 v) {
    __half hx = __float2half(v.x), hy = __float2half(v.y);
    __half2 hh; hh.x = hx; hh.y = hy;
    __half2 ll;
    ll.x = __float2half(v.x - __half2float(hx));
    ll.y = __float2half(v.y - __half2float(hy));
    ((__half2*)(H + rowoff))[lane] = hh;
    ((__half2*)(L + rowoff))[lane] = ll;
}

__global__ void prep_kernel(const float* __restrict__ freqs,
                            const float* __restrict__ q_scale,
                            const float* __restrict__ k_scale,
                            const float* __restrict__ mem_k,
                            const float* __restrict__ mem_v) {
    int w = (blockIdx.x * blockDim.x + threadIdx.x) >> 5;
    int lane = threadIdx.x & 31;
    const int MAIN = Bb * Nn * Hh;
    if (w < MAIN) {
        int b = w / (Nn * Hh); int r = w % (Nn * Hh);
        int n = r / Hh; int h = r % Hh;
        size_t src = (size_t)(b * Nn + n) * DIMm + h * DHh;
        float2 q2 = ((const float2*)&g_Qraw[src])[lane];
        float2 k2 = ((const float2*)&g_Kraw[src])[lane];
        float2 v2 = ((const float2*)&g_Vraw[src])[lane];
        float ssq = q2.x * q2.x + q2.y * q2.y;
        float ssk = k2.x * k2.x + k2.y * k2.y;
        for (int o = 16; o > 0; o >>= 1) {
            ssq += __shfl_xor_sync(~0u, ssq, o);
            ssk += __shfl_xor_sync(~0u, ssk, o);
        }
        float invq = 1.0f / fmaxf(sqrtf(ssq), 1e-12f);
        float invk = 1.0f / fmaxf(sqrtf(ssk), 1e-12f);
        float sqx = q_scale[h * DHh + 2 * lane], sqy = q_scale[h * DHh + 2 * lane + 1];
        float skx = k_scale[h * DHh + 2 * lane], sky = k_scale[h * DHh + 2 * lane + 1];
        float qx = q2.x * invq * sqx, qy = q2.y * invq * sqy;
        float kx = k2.x * invk * skx, ky = k2.y * invk * sky;
        float f = freqs[n * DHh + 2 * lane];
        float cf = cosf(f), sf = sinf(f);
        float2 qo = {qx * cf - qy * sf, qy * cf + qx * sf};
        float2 ko = {kx * cf - ky * sf, ky * cf + kx * sf};
        int bh = b * Hh + h;
        wr_hl(g_Qh, g_Ql, ((size_t)bh * Nn + n) * DHh, lane, qo);
        wr_hl(g_Kh, g_Kl, ((size_t)bh * PJ + Mm + n) * DHh, lane, ko);
        wr_hl16(g_Vh16, g_Vl16, ((size_t)bh * PJ + Mm + n) * DHh, lane, v2);
    } else {
        int w2 = w - MAIN;
        if (w2 < Bb * Hh * Mm) {
            int b = w2 / (Hh * Mm); int r = w2 % (Hh * Mm);
            int h = r / Mm; int m = r % Mm;
            float2 mk = ((const float2*)&mem_k[(size_t)(h * Mm + m) * DHh])[lane];
            float2 mv = ((const float2*)&mem_v[(size_t)(h * Mm + m) * DHh])[lane];
            float ss = mk.x * mk.x + mk.y * mk.y;
            for (int o = 16; o > 0; o >>= 1) ss += __shfl_xor_sync(~0u, ss, o);
            float inv = 1.0f / fmaxf(sqrtf(ss), 1e-12f);
            float2 ko = {mk.x * inv * k_scale[h * DHh + 2 * lane],
                         mk.y * inv * k_scale[h * DHh + 2 * lane + 1]};
            int bh = b * Hh + h;
            wr_hl(g_Kh, g_Kl, ((size_t)bh * PJ + m) * DHh, lane, ko);
            wr_hl16(g_Vh16, g_Vl16, ((size_t)bh * PJ + m) * DHh, lane, mv);
        }
    }
}

// ---------------- dots = Q K^T (HMMA bf16 hi/lo, raw scores) ---------------
__global__ __launch_bounds__(128) void dots_hmma() {
    int bh = blockIdx.y;
    int x = blockIdx.x;
    int ib = 0;
#pragma unroll 1
    while (((ib + 1) * (ib + 4)) / 2 <= x) ib++;
    int jb = x - (ib * (ib + 3)) / 2;
    int i0 = ib * 64, j0 = jb * 64;
    __shared__ __align__(128) char sm[32768];
    uint32_t sb = smem_u32(sm);
    int t = threadIdx.x, lane = t & 31, w = t >> 5;
    const __nv_bfloat16* Qh = g_Qh + ((size_t)bh * Nn + i0) * DHh;
    const __nv_bfloat16* Ql = g_Ql + ((size_t)bh * Nn + i0) * DHh;
    const __nv_bfloat16* Kh = g_Kh + ((size_t)bh * PJ + j0) * DHh;
    const __nv_bfloat16* Kl = g_Kl + ((size_t)bh * PJ + j0) * DHh;
#pragma unroll
    for (int i = 0; i < 16; i++) {
        int idx = t + i * 128;
        int tile = idx >> 9;
        int ci = idx & 511, r = ci >> 3, c = ci & 7;
        const __nv_bfloat16* src = (tile == 0) ? Qh : (tile == 1) ? Ql
                                 : (tile == 2) ? Kh : Kl;
        cp_async16(sb + tile * 8192 + r * 128 + ((c ^ (r & 7)) << 4),
                   src + (size_t)r * DHh + c * 8);
    }
    cp_commit(); cp_wait0();
    __syncthreads();
    int m0 = w * 16;
    float acc[8][4] = {};
    int a_r = m0 + ((lane >> 3) & 1) * 8 + (lane & 7);
    int a_c2 = lane >> 4;
    int b_r = (lane & 7) + ((lane >> 4) & 1) * 8;
    int b_c2 = (lane >> 3) & 1;
    uint32_t aH = sb, aL = sb + 8192, bH = sb + 16384, bL = sb + 24576;
#pragma unroll
    for (int pass = 0; pass < 3; pass++) {
        uint32_t at = (pass == 2) ? aL : aH;
        uint32_t bt = (pass == 1) ? bL : bH;
#pragma unroll
        for (int kk = 0; kk < 4; kk++) {
            uint32_t fA[4];
            int c = kk * 2 + a_c2;
            ldsm_x4(fA, at + a_r * 128 + ((c ^ (a_r & 7)) << 4));
#pragma unroll
            for (int ng = 0; ng < 4; ng++) {
                uint32_t fB[4];
                int n = ng * 16 + b_r;
                int cb = kk * 2 + b_c2;
                ldsm_x4(fB, bt + n * 128 + ((cb ^ (n & 7)) << 4));
                mma16816(acc[ng * 2], fA, fB);
                mma16816(acc[ng * 2 + 1], fA, fB + 2);
            }
        }
    }
    int row = i0 + m0 + (lane >> 2);
    int cb = (lane & 3) * 2;
    float* D = g_dots + (size_t)bh * Nn * NJ;
#pragma unroll
    for (int nb = 0; nb < 8; nb++) {
        int col = j0 + nb * 8 + cb;
        if (col < NJ) {
            float2 v0 = {acc[nb][0], acc[nb][1]};
            float2 v1 = {acc[nb][2], acc[nb][3]};
            *(float2*)&D[(size_t)row * NJ + col] = v0;
            *(float2*)&D[(size_t)(row + 8) * NJ + col] = v1;
        }
    }
}

// --- fused: pre-mix -> softmax -> post-mix(inv folded) -> fp16 P -----------
// longest rows scheduled FIRST (i = Nn-1-blockIdx.x) to minimize wave tail
__global__ __launch_bounds__(512) void softmax_kernel(const float* __restrict__ W_pre,
                                                      const float* __restrict__ W_post) {
    extern __shared__ float smemf[];
    float* sD = smemf;                 // 16 * NJ
    float* sWpre = sD + 16 * NJ;       // 256
    float* sWpost = sWpre + 256;       // 256
    float* sInv = sWpost + 256;        // 16
    int t = threadIdx.x;
    int i = Nn - 1 - blockIdx.x, b = blockIdx.y;
    if (t < 256) { sWpre[t] = W_pre[t] * QK_SCALE; sWpost[t] = W_post[t]; }
    int jcount = i + 17;
    int g = t >> 5, lane = t & 31;
    int jsel = (t & 255) * 2;          // 0..510
    int g8 = (t >> 8) * 8;             // 0 or 8

    // ---- load all 16 rows (warp w owns head w), float4 coalesced ----
    {
        const float* src = &g_dots[((size_t)(b * Hh + g) * Nn + i) * NJ];
        float* dst = sD + g * NJ;
        for (int j = lane * 4; j < jcount; j += 128)
            *(float4*)&dst[j] = *(const float4*)&src[j];
    }
    __syncthreads();

    // ---- in-place pre-mix, uniform iterations with read/write barrier ----
    {
        int nIter = (jcount + 511) / 512;
        for (int it = 0; it < nIter; it++) {
            int j = it * 512 + jsel;
            bool act = (j < jcount);
            float2 col[16];
            if (act) {
#pragma unroll
                for (int h = 0; h < 16; h++) col[h] = *(const float2*)&sD[h * NJ + j];
            }
            __syncthreads();
            if (act) {
#pragma unroll
                for (int gg = 0; gg < 8; gg++) {
                    int gd = g8 + gg;
                    float ax = 0.f, ay = 0.f;
#pragma unroll
                    for (int h = 0; h < 16; h++) {
                        float wv = sWpre[gd * 16 + h];
                        ax += wv * col[h].x; ay += wv * col[h].y;
                    }
                    float2 o2 = {ax, ay};
                    *(float2*)&sD[gd * NJ + j] = o2;
                }
            }
            __syncthreads();
        }
    }

    // ---- softmax: warp g owns head g; store unnormalized e + inv ----
    {
        float* row = sD + g * NJ;
        float m = -FLT_MAX;
        for (int j = lane; j < jcount; j += 32) m = fmaxf(m, row[j]);
#pragma unroll
        for (int o = 16; o > 0; o >>= 1) m = fmaxf(m, __shfl_xor_sync(~0u, m, o));
        float l = 0.f;
        for (int j = lane; j < jcount; j += 32) {
            float e = __expf(row[j] - m); row[j] = e; l += e;
        }
#pragma unroll
        for (int o = 16; o > 0; o >>= 1) l += __shfl_xor_sync(~0u, l, o);
        if (lane == 0) sInv[g] = 1.f / l;
    }
    __syncthreads();

    // ---- post-mix (inv folded), direct fp16 write, zero fill --------------
    int jendP = (i & ~127) + 192;
    size_t pbase = ((size_t)(b * Hh) * Nn + i) * PJ;
    float wp[16];
#pragma unroll 1
    for (int gg = 0; gg < 8; gg++) {
        int gd = g8 + gg;
#pragma unroll
        for (int h = 0; h < 16; h++) wp[h] = sWpost[gd * 16 + h] * sInv[h];
        __half* ph = (__half*)&g_P16[pbase + (size_t)gd * Nn * PJ];
        for (int j = jsel; j < jendP; j += 512) {
            float ax = 0.f, ay = 0.f;
            if (j < jcount) {
#pragma unroll
                for (int h = 0; h < 16; h++) {
                    float2 d2 = *(const float2*)&sD[h * NJ + j];
                    ax += wp[h] * d2.x; ay += wp[h] * d2.y;
                }
                if (j + 1 >= jcount) ay = 0.f;
            }
            __half2 hh; hh.x = __float2half(ax); hh.y = __float2half(ay);
            *(__half2*)&ph[j] = hh;
        }
    }
}

// ------- O_g = P_g @ V_g (fp16), 128-row i-tiles, 8 warps ------------------
// longest tiles scheduled FIRST (i0 reversed) to minimize wave tail
__global__ __launch_bounds__(256) void av_hmma() {
    int bh = blockIdx.y;
    int i0 = (int)(gridDim.x - 1 - blockIdx.x) * 128;
    int ntiles = (i0 >> 6) + 3;
    extern __shared__ __align__(128) char sm[];   // 2 x 32768
    uint32_t sb = smem_u32(sm);
    int t = threadIdx.x, lane = t & 31, w = t >> 5;
    const __half* P = g_P16 + ((size_t)bh * Nn + i0) * PJ;
    const __half* Vh = g_Vh16 + (size_t)bh * PJ * DHh;
    const __half* Vl = g_Vl16 + (size_t)bh * PJ * DHh;

    auto issue = [&](int jt) {
        uint32_t st = sb + (uint32_t)(jt & 1) * 32768u;
#pragma unroll
        for (int i = 0; i < 8; i++) {
            int idx = t + i * 256;
            const __half* g;
            uint32_t soff;
            if (idx < 1024) {
                int r = idx >> 3, c = idx & 7;
                g = P + (size_t)r * PJ + jt * 64 + c * 8;
                soff = (uint32_t)(r * 128 + ((c ^ (r & 7)) << 4));
            } else if (idx < 1536) {
                int ci = idx - 1024, r = ci >> 3, c = ci & 7;
                g = Vh + (size_t)(jt * 64 + r) * DHh + c * 8;
                soff = 16384u + (uint32_t)(r * 128 + ((c ^ (r & 7)) << 4));
            } else {
                int ci = idx - 1536, r = ci >> 3, c = ci & 7;
                g = Vl + (size_t)(jt * 64 + r) * DHh + c * 8;
                soff = 24576u + (uint32_t)(r * 128 + ((c ^ (r & 7)) << 4));
            }
            cp_async16(st + soff, g);
        }
        cp_commit();
    };

    issue(0);
    float acc[8][4] = {};
    int m0 = w * 16;
    int a_r = m0 + ((lane >> 3) & 1) * 8 + (lane & 7);
    int a_c2 = lane >> 4;
    int v_j = (lane & 7) + ((lane >> 3) & 1) * 8;
    int v_c2 = lane >> 4;
    for (int jt = 0; jt < ntiles; jt++) {
        if (jt + 1 < ntiles) { issue(jt + 1); cp_wait1(); } else cp_wait0();
        __syncthreads();
        uint32_t st = sb + (uint32_t)(jt & 1) * 32768u;
        uint32_t pA = st, vH = st + 16384, vL = st + 24576;
#pragma unroll
        for (int kk = 0; kk < 4; kk++) {
            uint32_t fA[4];
            int c = kk * 2 + a_c2;
            ldsm_x4(fA, pA + a_r * 128 + ((c ^ (a_r & 7)) << 4));
#pragma unroll
            for (int dg = 0; dg < 4; dg++) {
                uint32_t fVh[4], fVl[4];
                int jr = kk * 16 + v_j;
                int cv = dg * 2 + v_c2;
                ldsm_x4_t(fVh, vH + jr * 128 + ((cv ^ (jr & 7)) << 4));
                ldsm_x4_t(fVl, vL + jr * 128 + ((cv ^ (jr & 7)) << 4));
                mma16816h(acc[dg * 2],     fA, fVh);
                mma16816h(acc[dg * 2 + 1], fA, fVh + 2);
                mma16816h(acc[dg * 2],     fA, fVl);
                mma16816h(acc[dg * 2 + 1], fA, fVl + 2);
            }
        }
        __syncthreads();
    }
    float* O = g_Ohd + ((size_t)bh * Nn + i0) * DHh;
    int row = m0 + (lane >> 2), cb = (lane & 3) * 2;
#pragma unroll
    for (int db = 0; db < 8; db++) {
        float2 v0 = {acc[db][0], acc[db][1]};
        float2 v1 = {acc[db][2], acc[db][3]};
        *(float2*)&O[(size_t)row * DHh + db * 8 + cb] = v0;
        *(float2*)&O[(size_t)(row + 8) * DHh + db * 8 + cb] = v1;
    }
}

// ------- gates only (post-mix already applied) -> fp16 ---------------------
__global__ __launch_bounds__(128) void mix_gate(const float* __restrict__ b_h,
                                                const float* __restrict__ b_v) {
    int rowid = blockIdx.x;             // 0..4095
    int b = rowid >> 10, n = rowid & 1023;
    int t = threadIdx.x;
#pragma unroll
    for (int k = 0; k < 8; k++) {
        int idx = t + k * 128; int g = idx >> 6, d = idx & 63;
        float a = g_Ohd[((size_t)(b * Hh + g) * Nn + n) * DHh + d];
        float hg = 1.f / (1.f + __expf(-(g_hgraw[(size_t)rowid * 16 + g] + b_h[g])));
        float vg = 1.f / (1.f + __expf(-(g_vgraw[(size_t)rowid * 1024 + idx] + b_v[idx])));
        g_of[(size_t)rowid * 1024 + idx] = __float2half(a * hg * vg);
    }
}

// ---------------------------------------------------------------------------
extern "C" void kernel_launch(void* const* d_in, const int* in_sizes, int n_in,
                              void* d_out, int out_size) {
    const float* x       = (const float*)d_in[0];
    const float* freqs   = (const float*)d_in[1];
    const float* Wq      = (const float*)d_in[2];
    const float* Wk      = (const float*)d_in[3];
    const float* Wv      = (const float*)d_in[4];
    const float* q_scale = (const float*)d_in[5];
    const float* k_scale = (const float*)d_in[6];
    const float* mem_k   = (const float*)d_in[7];
    const float* mem_v   = (const float*)d_in[8];
    const float* W_pre   = (const float*)d_in[9];
    const float* W_post  = (const float*)d_in[10];
    const float* W_hgate = (const float*)d_in[11];
    const float* b_hgate = (const float*)d_in[12];
    const float* W_vgate = (const float*)d_in[13];
    const float* b_vgate = (const float*)d_in[14];
    const float* Wo      = (const float*)d_in[15];
    float* out = (float*)d_out;

    float *Qraw, *Kraw, *Vraw, *vgraw;
    __nv_bfloat16 *Ahi, *Alo;
    __half *xf, *of;
    cudaGetSymbolAddress((void**)&Qraw, g_Qraw);
    cudaGetSymbolAddress((void**)&Kraw, g_Kraw);
    cudaGetSymbolAddress((void**)&Vraw, g_Vraw);
    cudaGetSymbolAddress((void**)&vgraw, g_vgraw);
    cudaGetSymbolAddress((void**)&Ahi, g_Ahi);
    cudaGetSymbolAddress((void**)&Alo, g_Alo);
    cudaGetSymbolAddress((void**)&xf, g_xf);
    cudaGetSymbolAddress((void**)&of, g_of);

    conv_x<<<ROWS * DIMm / 1024, 256>>>(x);
    conv_w_t<<<dim3(32, 32, 5), 256>>>(Wq, Wk, Wv, W_vgate, Wo);
    hg_t<<<64, 256>>>(W_hgate);

    cudaFuncSetAttribute(mma_gemm_bf, cudaFuncAttributeMaxDynamicSharedMemorySize, 65536);
    cudaFuncSetAttribute(mma_gemm_f16, cudaFuncAttributeMaxDynamicSharedMemorySize, 49152);
    mma_gemm_bf<<<dim3(DIMm / 128, ROWS / 128, 2), 256, 65536>>>(Ahi, Alo, Qraw, Kraw);
    mma_gemm_f16<<<dim3(DIMm / 128, ROWS / 128, 2), 256, 49152>>>(xf, 0, Vraw, vgraw);
    hgate_warp<<<ROWS / 4, 128>>>(x);

    int warps = Bb * Nn * Hh + Bb * Hh * Mm;
    prep_kernel<<<(warps + 7) / 8, 256>>>(freqs, q_scale, k_scale, mem_k, mem_v);

    dots_hmma<<<dim3(152, 64), 128>>>();

    size_t smem_bytes = (16 * NJ + 512 + 16) * sizeof(float);
    cudaFuncSetAttribute(softmax_kernel, cudaFuncAttributeMaxDynamicSharedMemorySize,
                         (int)smem_bytes);
    softmax_kernel<<<dim3(Nn, Bb), 512, smem_bytes>>>(W_pre, W_post);

    cudaFuncSetAttribute(av_hmma, cudaFuncAttributeMaxDynamicSharedMemorySize, 65536);
    av_hmma<<<dim3(Nn / 128, 64), 256, 65536>>>();

    mix_gate<<<ROWS, 128>>>(b_hgate, b_vgate);

    mma_gemm_f16<<<dim3(DIMm / 128, ROWS / 128, 1), 256, 49152>>>(of, 2, out, out);
}

// round 16
// speedup vs baseline: 1.0256x; 1.0256x over previous
#include <cuda_runtime.h>
#include <cuda_bf16.h>
#include <cuda_fp16.h>
#include <math.h>
#include <float.h>
#include <stdint.h>

#define Bb   4
#define Nn   1024
#define DIMm 1024
#define Hh   16
#define DHh  64
#define Mm   16
#define NJ   1040          // M + N
#define PJ   1088          // padded kv length (multiple of 64)
#define ROWS 4096          // B*N
#define QK_SCALE 10.0f

// ===================== scratch =============================================
__device__ float g_Qraw[(size_t)ROWS * DIMm];
__device__ float g_Kraw[(size_t)ROWS * DIMm];
__device__ float g_Vraw[(size_t)ROWS * DIMm];
__device__ float g_vgraw[(size_t)ROWS * DIMm];
__device__ float g_hgraw[(size_t)ROWS * Hh];
__device__ float g_dots[(size_t)64 * Nn * NJ];
__device__ float g_Ohd[(size_t)64 * Nn * DHh];
__device__ float g_Whgt[16 * 1024];
__device__ __nv_bfloat16 g_Qh[(size_t)64 * Nn * DHh];
__device__ __nv_bfloat16 g_Ql[(size_t)64 * Nn * DHh];
__device__ __nv_bfloat16 g_Kh[(size_t)64 * PJ * DHh];   // pad rows stay zero
__device__ __nv_bfloat16 g_Kl[(size_t)64 * PJ * DHh];
__device__ __half g_Vh16[(size_t)64 * PJ * DHh];        // pad rows stay zero
__device__ __half g_Vl16[(size_t)64 * PJ * DHh];
__device__ __half g_P16[(size_t)64 * Nn * PJ];
__device__ __nv_bfloat16 g_Ahi[(size_t)ROWS * DIMm];    // x bf16 hi/lo (Q,K path)
__device__ __nv_bfloat16 g_Alo[(size_t)ROWS * DIMm];
__device__ __half g_xf[(size_t)ROWS * DIMm];            // x fp16 (V,vgate path)
__device__ __half g_of[(size_t)ROWS * DIMm];            // gated out fp16 (Wo path)
__device__ __nv_bfloat16 g_Wthi[(size_t)2 * DIMm * DIMm];  // Wq, Wk (bf16 hi/lo)
__device__ __nv_bfloat16 g_Wtlo[(size_t)2 * DIMm * DIMm];
__device__ __half g_Wfhi[(size_t)3 * DIMm * DIMm];         // Wv, Wvg, Wo (fp16 hi/lo)
__device__ __half g_Wflo[(size_t)3 * DIMm * DIMm];

// ===================== PTX helpers (base ISA only) =========================
__device__ __forceinline__ uint32_t smem_u32(const void* p) {
    uint32_t a;
    asm("{ .reg .u64 tmp; cvta.to.shared.u64 tmp, %1; cvt.u32.u64 %0, tmp; }"
        : "=r"(a) : "l"(p));
    return a;
}
__device__ __forceinline__ void cp_async16(uint32_t s, const void* g) {
    asm volatile("cp.async.cg.shared.global [%0], [%1], 16;" :: "r"(s), "l"(g));
}
__device__ __forceinline__ void cp_commit() {
    asm volatile("cp.async.commit_group;" ::: "memory");
}
__device__ __forceinline__ void cp_wait1() {
    asm volatile("cp.async.wait_group 1;" ::: "memory");
}
__device__ __forceinline__ void cp_wait0() {
    asm volatile("cp.async.wait_group 0;" ::: "memory");
}
__device__ __forceinline__ void ldsm_x4(uint32_t* r, uint32_t addr) {
    asm volatile("ldmatrix.sync.aligned.m8n8.x4.shared.b16 {%0,%1,%2,%3}, [%4];"
                 : "=r"(r[0]), "=r"(r[1]), "=r"(r[2]), "=r"(r[3]) : "r"(addr));
}
__device__ __forceinline__ void ldsm_x4_t(uint32_t* r, uint32_t addr) {
    asm volatile("ldmatrix.sync.aligned.m8n8.x4.trans.shared.b16 {%0,%1,%2,%3}, [%4];"
                 : "=r"(r[0]), "=r"(r[1]), "=r"(r[2]), "=r"(r[3]) : "r"(addr));
}
__device__ __forceinline__ void mma16816(float* d, const uint32_t* a, const uint32_t* b) {
    asm volatile(
        "mma.sync.aligned.m16n8k16.row.col.f32.bf16.bf16.f32 "
        "{%0,%1,%2,%3}, {%4,%5,%6,%7}, {%8,%9}, {%0,%1,%2,%3};"
        : "+f"(d[0]), "+f"(d[1]), "+f"(d[2]), "+f"(d[3])
        : "r"(a[0]), "r"(a[1]), "r"(a[2]), "r"(a[3]), "r"(b[0]), "r"(b[1]));
}
__device__ __forceinline__ void mma16816h(float* d, const uint32_t* a, const uint32_t* b) {
    asm volatile(
        "mma.sync.aligned.m16n8k16.row.col.f32.f16.f16.f32 "
        "{%0,%1,%2,%3}, {%4,%5,%6,%7}, {%8,%9}, {%0,%1,%2,%3};"
        : "+f"(d[0]), "+f"(d[1]), "+f"(d[2]), "+f"(d[3])
        : "r"(a[0]), "r"(a[1]), "r"(a[2]), "r"(a[3]), "r"(b[0]), "r"(b[1]));
}

// ===================== convert kernels =====================================
__global__ void conv_x(const float* __restrict__ src) {
    int i = blockIdx.x * 256 + threadIdx.x;
    float4 v = ((const float4*)src)[i];
    float f[4] = {v.x, v.y, v.z, v.w};
    __nv_bfloat16 h[4], l[4];
    __half x16[4];
#pragma unroll
    for (int k = 0; k < 4; k++) {
        h[k] = __float2bfloat16(f[k]);
        l[k] = __float2bfloat16(f[k] - __bfloat162float(h[k]));
        x16[k] = __float2half(f[k]);
    }
    __nv_bfloat162 p0, p1, q0, q1;
    p0.x = h[0]; p0.y = h[1]; p1.x = h[2]; p1.y = h[3];
    q0.x = l[0]; q0.y = l[1]; q1.x = l[2]; q1.y = l[3];
    ((__nv_bfloat162*)g_Ahi)[i * 2] = p0; ((__nv_bfloat162*)g_Ahi)[i * 2 + 1] = p1;
    ((__nv_bfloat162*)g_Alo)[i * 2] = q0; ((__nv_bfloat162*)g_Alo)[i * 2 + 1] = q1;
    __half2 r0, r1; r0.x = x16[0]; r0.y = x16[1]; r1.x = x16[2]; r1.y = x16[3];
    ((__half2*)g_xf)[i * 2] = r0; ((__half2*)g_xf)[i * 2 + 1] = r1;
}

__global__ void conv_w_t(const float* __restrict__ W0, const float* __restrict__ W1,
                         const float* __restrict__ W2, const float* __restrict__ W3,
                         const float* __restrict__ W4) {
    const float* Ws[5] = {W0, W1, W2, W3, W4};
    int z = blockIdx.z;
    const float* W = Ws[z];
    __shared__ float tile[32][33];
    int k0 = blockIdx.y * 32, n0 = blockIdx.x * 32;
    int c = threadIdx.x & 31, r8 = threadIdx.x >> 5;
#pragma unroll
    for (int i = 0; i < 4; i++) {
        int r = r8 + i * 8;
        tile[r][c] = W[(size_t)(k0 + r) * DIMm + n0 + c];
    }
    __syncthreads();
    if (z < 2) {
        __nv_bfloat16* hi = g_Wthi + (size_t)z * DIMm * DIMm;
        __nv_bfloat16* lo = g_Wtlo + (size_t)z * DIMm * DIMm;
#pragma unroll
        for (int i = 0; i < 4; i++) {
            int r = r8 + i * 8;
            float v = tile[c][r];
            __nv_bfloat16 h = __float2bfloat16(v);
            hi[(size_t)(n0 + r) * DIMm + k0 + c] = h;
            lo[(size_t)(n0 + r) * DIMm + k0 + c] = __float2bfloat16(v - __bfloat162float(h));
        }
    } else {
        __half* hi = g_Wfhi + (size_t)(z - 2) * DIMm * DIMm;
        __half* lo = g_Wflo + (size_t)(z - 2) * DIMm * DIMm;
#pragma unroll
        for (int i = 0; i < 4; i++) {
            int r = r8 + i * 8;
            float v = tile[c][r];
            __half h = __float2half(v);
            hi[(size_t)(n0 + r) * DIMm + k0 + c] = h;
            lo[(size_t)(n0 + r) * DIMm + k0 + c] = __float2half(v - __half2float(h));
        }
    }
}

__global__ void hg_t(const float* __restrict__ W) {
    int idx = blockIdx.x * 256 + threadIdx.x;   // 16384
    int h = idx >> 10, k = idx & 1023;
    g_Whgt[idx] = W[k * 16 + h];
}

// ========== bf16 hi/lo 3-pass GEMM (Q,K), CTA 128x128, k-stage 64 ==========
// stage (64KB): Ahi[0,16K) Alo[16K,32K) Bh[32K,48K) Bl[48K,64K); rows 128B
__global__ __launch_bounds__(256)
void mma_gemm_bf(const __nv_bfloat16* __restrict__ Ahi, const __nv_bfloat16* __restrict__ Alo,
                 float* __restrict__ C0, float* __restrict__ C1) {
    extern __shared__ __align__(1024) char smem[];
    uint32_t sbase = smem_u32(smem);
    int z = blockIdx.z;
    const __nv_bfloat16* Bh = g_Wthi + (size_t)z * DIMm * DIMm;
    const __nv_bfloat16* Bl = g_Wtlo + (size_t)z * DIMm * DIMm;
    float* C = (z == 0) ? C0 : C1;

    int t = threadIdx.x;
    int lane = t & 31, w = t >> 5;
    int wm = w >> 2, wn = w & 3;
    int i0 = blockIdx.y * 128, n0 = blockIdx.x * 128;

    float acc[4][4][4] = {};

    int a_rl = ((lane >> 3) & 1) * 8 + (lane & 7);
    int a_ch = lane >> 4;
    int b_nl = (lane & 7) + ((lane >> 4) & 1) * 8;
    int b_ch = (lane >> 3) & 1;

    auto issue_load = [&](int ks) {
        uint32_t stage = sbase + (uint32_t)(ks & 1) * 65536u;
        int k0 = ks * 64;
#pragma unroll
        for (int i = 0; i < 16; i++) {
            int idx = i * 256 + t;              // 0..4095
            int tile = idx >> 10;               // 0 Ahi, 1 Alo, 2 Bh, 3 Bl
            int ci = idx & 1023, r = ci >> 3, c = ci & 7;
            const __nv_bfloat16* src = (tile == 0) ? Ahi : (tile == 1) ? Alo
                                     : (tile == 2) ? Bh : Bl;
            int rb = (tile < 2) ? i0 : n0;
            const __nv_bfloat16* g = src + (size_t)(rb + r) * DIMm + k0 + c * 8;
            uint32_t s = stage + (uint32_t)(tile * 16384 + r * 128 +
                          ((c ^ (r & 7)) << 4));
            cp_async16(s, g);
        }
        cp_commit();
    };

    issue_load(0);
    const int NS = DIMm / 64;                   // 16
    for (int ks = 0; ks < NS; ks++) {
        if (ks + 1 < NS) issue_load(ks + 1);
        if (ks + 1 < NS) cp_wait1(); else cp_wait0();
        __syncthreads();
        uint32_t sb = sbase + (uint32_t)(ks & 1) * 65536u;
        uint32_t aH = sb, aL = sb + 16384, bH = sb + 32768, bL = sb + 49152;
#pragma unroll
        for (int kk = 0; kk < 4; kk++) {
            int c0 = kk * 2;
            uint32_t fBh[2][4], fBl[2][4], fA[4][4];
#pragma unroll
            for (int ng = 0; ng < 2; ng++) {
                int n = wn * 32 + ng * 16 + b_nl;
                int c = c0 + b_ch;
                uint32_t off = (uint32_t)(n * 128 + ((c ^ (n & 7)) << 4));
                ldsm_x4(fBh[ng], bH + off);
                ldsm_x4(fBl[ng], bL + off);
            }
#pragma unroll
            for (int mt = 0; mt < 4; mt++) {
                int r = wm * 64 + mt * 16 + a_rl;
                int c = c0 + a_ch;
                uint32_t off = (uint32_t)(r * 128 + ((c ^ (r & 7)) << 4));
                ldsm_x4(fA[mt], aH + off);
            }
#pragma unroll
            for (int mt = 0; mt < 4; mt++)
#pragma unroll
                for (int nt = 0; nt < 4; nt++) {
                    mma16816(acc[mt][nt], fA[mt], &fBh[nt >> 1][(nt & 1) * 2]);
                    mma16816(acc[mt][nt], fA[mt], &fBl[nt >> 1][(nt & 1) * 2]);
                }
#pragma unroll
            for (int mt = 0; mt < 4; mt++) {
                int r = wm * 64 + mt * 16 + a_rl;
                int c = c0 + a_ch;
                uint32_t off = (uint32_t)(r * 128 + ((c ^ (r & 7)) << 4));
                ldsm_x4(fA[mt], aL + off);
            }
#pragma unroll
            for (int mt = 0; mt < 4; mt++)
#pragma unroll
                for (int nt = 0; nt < 4; nt++)
                    mma16816(acc[mt][nt], fA[mt], &fBh[nt >> 1][(nt & 1) * 2]);
        }
        __syncthreads();
    }

    int row0 = i0 + wm * 64 + (lane >> 2);
    int col0 = n0 + wn * 32 + (lane & 3) * 2;
#pragma unroll
    for (int mt = 0; mt < 4; mt++)
#pragma unroll
        for (int nt = 0; nt < 4; nt++) {
            int r = row0 + mt * 16, cc = col0 + nt * 8;
            float2 v0 = {acc[mt][nt][0], acc[mt][nt][1]};
            float2 v1 = {acc[mt][nt][2], acc[mt][nt][3]};
            *(float2*)&C[(size_t)r * DIMm + cc] = v0;
            *(float2*)&C[(size_t)(r + 8) * DIMm + cc] = v1;
        }
}

// ========== fp16 GEMM (V: 2-pass; vgate: 1-pass; Wo: 2-pass), k-stage 64 ===
// stage (48KB): A[0,16K) Bh[16K,32K) Bl[32K,48K); rows 128B
__global__ __launch_bounds__(256)
void mma_gemm_f16(const __half* __restrict__ Af, int wbase,
                  float* __restrict__ C0, float* __restrict__ C1) {
    extern __shared__ __align__(1024) char smem[];
    uint32_t sbase = smem_u32(smem);
    int z = blockIdx.z;
    int widx = wbase + z;
    int npass = (widx == 1) ? 1 : 2;
    const __half* Bh = g_Wfhi + (size_t)widx * DIMm * DIMm;
    const __half* Bl = g_Wflo + (size_t)widx * DIMm * DIMm;
    float* C = (z == 0) ? C0 : C1;

    int t = threadIdx.x;
    int lane = t & 31, w = t >> 5;
    int wm = w >> 2, wn = w & 3;
    int i0 = blockIdx.y * 128, n0 = blockIdx.x * 128;

    float acc[4][4][4] = {};

    int a_rl = ((lane >> 3) & 1) * 8 + (lane & 7);
    int a_ch = lane >> 4;
    int b_nl = (lane & 7) + ((lane >> 4) & 1) * 8;
    int b_ch = (lane >> 3) & 1;

    auto issue_load = [&](int ks) {
        uint32_t stage = sbase + (uint32_t)(ks & 1) * 49152u;
        int k0 = ks * 64;
#pragma unroll
        for (int i = 0; i < 12; i++) {
            int idx = i * 256 + t;              // 0..3071
            int tile = idx >> 10;               // 0 A, 1 Bh, 2 Bl
            if (tile == 2 && npass == 1) continue;
            int ci = idx & 1023, r = ci >> 3, c = ci & 7;
            const __half* g = (tile == 0) ? Af + (size_t)(i0 + r) * DIMm + k0 + c * 8
                            : (tile == 1) ? Bh + (size_t)(n0 + r) * DIMm + k0 + c * 8
                                          : Bl + (size_t)(n0 + r) * DIMm + k0 + c * 8;
            uint32_t s = stage + (uint32_t)(tile * 16384 + r * 128 +
                          ((c ^ (r & 7)) << 4));
            cp_async16(s, g);
        }
        cp_commit();
    };

    issue_load(0);
    const int NS = DIMm / 64;                   // 16
    for (int ks = 0; ks < NS; ks++) {
        if (ks + 1 < NS) issue_load(ks + 1);
        if (ks + 1 < NS) cp_wait1(); else cp_wait0();
        __syncthreads();
        uint32_t sb = sbase + (uint32_t)(ks & 1) * 49152u;
        uint32_t aF = sb, bH = sb + 16384, bL = sb + 32768;
#pragma unroll
        for (int kk = 0; kk < 4; kk++) {
            int c0 = kk * 2;
            uint32_t fB[2][4], fA[4][4];
#pragma unroll
            for (int ng = 0; ng < 2; ng++) {
                int n = wn * 32 + ng * 16 + b_nl;
                int c = c0 + b_ch;
                ldsm_x4(fB[ng], bH + (uint32_t)(n * 128 + ((c ^ (n & 7)) << 4)));
            }
#pragma unroll
            for (int mt = 0; mt < 4; mt++) {
                int r = wm * 64 + mt * 16 + a_rl;
                int c = c0 + a_ch;
                ldsm_x4(fA[mt], aF + (uint32_t)(r * 128 + ((c ^ (r & 7)) << 4)));
            }
#pragma unroll
            for (int mt = 0; mt < 4; mt++)
#pragma unroll
                for (int nt = 0; nt < 4; nt++)
                    mma16816h(acc[mt][nt], fA[mt], &fB[nt >> 1][(nt & 1) * 2]);
            if (npass == 2) {
#pragma unroll
                for (int ng = 0; ng < 2; ng++) {
                    int n = wn * 32 + ng * 16 + b_nl;
                    int c = c0 + b_ch;
                    ldsm_x4(fB[ng], bL + (uint32_t)(n * 128 + ((c ^ (n & 7)) << 4)));
                }
#pragma unroll
                for (int mt = 0; mt < 4; mt++)
#pragma unroll
                    for (int nt = 0; nt < 4; nt++)
                        mma16816h(acc[mt][nt], fA[mt], &fB[nt >> 1][(nt & 1) * 2]);
            }
        }
        __syncthreads();
    }

    int row0 = i0 + wm * 64 + (lane >> 2);
    int col0 = n0 + wn * 32 + (lane & 3) * 2;
#pragma unroll
    for (int mt = 0; mt < 4; mt++)
#pragma unroll
        for (int nt = 0; nt < 4; nt++) {
            int r = row0 + mt * 16, cc = col0 + nt * 8;
            float2 v0 = {acc[mt][nt][0], acc[mt][nt][1]};
            float2 v1 = {acc[mt][nt][2], acc[mt][nt][3]};
            *(float2*)&C[(size_t)r * DIMm + cc] = v0;
            *(float2*)&C[(size_t)(r + 8) * DIMm + cc] = v1;
        }
}

// ---------------- head-gate: warp per row ----------------------------------
__global__ __launch_bounds__(128) void hgate_warp(const float* __restrict__ x) {
    int w = blockIdx.x * 4 + (threadIdx.x >> 5);
    int l = threadIdx.x & 31;
    float acc[16] = {};
    const float* xr = x + (size_t)w * 1024;
#pragma unroll
    for (int i = 0; i < 8; i++) {
        float4 xv = *(const float4*)&xr[i * 128 + l * 4];
#pragma unroll
        for (int h = 0; h < 16; h++) {
            float4 wv = *(const float4*)&g_Whgt[h * 1024 + i * 128 + l * 4];
            acc[h] += xv.x * wv.x + xv.y * wv.y + xv.z * wv.z + xv.w * wv.w;
        }
    }
#pragma unroll
    for (int h = 0; h < 16; h++)
#pragma unroll
        for (int o = 16; o > 0; o >>= 1) acc[h] += __shfl_xor_sync(~0u, acc[h], o);
    if (l == 0) {
#pragma unroll
        for (int h = 0; h < 16; h++) g_hgraw[(size_t)w * 16 + h] = acc[h];
    }
}

// ---------------- l2norm + scale + rope -> split layouts -------------------
__device__ __forceinline__ void wr_hl(__nv_bfloat16* H, __nv_bfloat16* L,
                                      size_t rowoff, int lane, float2 v) {
    __nv_bfloat16 hx = __float2bfloat16(v.x), hy = __float2bfloat16(v.y);
    __nv_bfloat162 hh; hh.x = hx; hh.y = hy;
    __nv_bfloat162 ll;
    ll.x = __float2bfloat16(v.x - __bfloat162float(hx));
    ll.y = __float2bfloat16(v.y - __bfloat162float(hy));
    ((__nv_bfloat162*)(H + rowoff))[lane] = hh;
    ((__nv_bfloat162*)(L + rowoff))[lane] = ll;
}
__device__ __forceinline__ void wr_hl16(__half* H, __half* L,
                                        size_t rowoff, int lane, float2 v) {
    __half hx = __float2half(v.x), hy = __float2half(v.y);
    __half2 hh; hh.x = hx; hh.y = hy;
    __half2 ll;
    ll.x = __float2half(v.x - __half2float(hx));
    ll.y = __float2half(v.y - __half2float(hy));
    ((__half2*)(H + rowoff))[lane] = hh;
    ((__half2*)(L + rowoff))[lane] = ll;
}

__global__ void prep_kernel(const float* __restrict__ freqs,
                            const float* __restrict__ q_scale,
                            const float* __restrict__ k_scale,
                            const float* __restrict__ mem_k,
                            const float* __restrict__ mem_v) {
    int w = (blockIdx.x * blockDim.x + threadIdx.x) >> 5;
    int lane = threadIdx.x & 31;
    const int MAIN = Bb * Nn * Hh;
    if (w < MAIN) {
        int b = w / (Nn * Hh); int r = w % (Nn * Hh);
        int n = r / Hh; int h = r % Hh;
        size_t src = (size_t)(b * Nn + n) * DIMm + h * DHh;
        float2 q2 = ((const float2*)&g_Qraw[src])[lane];
        float2 k2 = ((const float2*)&g_Kraw[src])[lane];
        float2 v2 = ((const float2*)&g_Vraw[src])[lane];
        float ssq = q2.x * q2.x + q2.y * q2.y;
        float ssk = k2.x * k2.x + k2.y * k2.y;
        for (int o = 16; o > 0; o >>= 1) {
            ssq += __shfl_xor_sync(~0u, ssq, o);
            ssk += __shfl_xor_sync(~0u, ssk, o);
        }
        float invq = 1.0f / fmaxf(sqrtf(ssq), 1e-12f);
        float invk = 1.0f / fmaxf(sqrtf(ssk), 1e-12f);
        float sqx = q_scale[h * DHh + 2 * lane], sqy = q_scale[h * DHh + 2 * lane + 1];
        float skx = k_scale[h * DHh + 2 * lane], sky = k_scale[h * DHh + 2 * lane + 1];
        float qx = q2.x * invq * sqx, qy = q2.y * invq * sqy;
        float kx = k2.x * invk * skx, ky = k2.y * invk * sky;
        float f = freqs[n * DHh + 2 * lane];
        float cf = cosf(f), sf = sinf(f);
        float2 qo = {qx * cf - qy * sf, qy * cf + qx * sf};
        float2 ko = {kx * cf - ky * sf, ky * cf + kx * sf};
        int bh = b * Hh + h;
        wr_hl(g_Qh, g_Ql, ((size_t)bh * Nn + n) * DHh, lane, qo);
        wr_hl(g_Kh, g_Kl, ((size_t)bh * PJ + Mm + n) * DHh, lane, ko);
        wr_hl16(g_Vh16, g_Vl16, ((size_t)bh * PJ + Mm + n) * DHh, lane, v2);
    } else {
        int w2 = w - MAIN;
        if (w2 < Bb * Hh * Mm) {
            int b = w2 / (Hh * Mm); int r = w2 % (Hh * Mm);
            int h = r / Mm; int m = r % Mm;
            float2 mk = ((const float2*)&mem_k[(size_t)(h * Mm + m) * DHh])[lane];
            float2 mv = ((const float2*)&mem_v[(size_t)(h * Mm + m) * DHh])[lane];
            float ss = mk.x * mk.x + mk.y * mk.y;
            for (int o = 16; o > 0; o >>= 1) ss += __shfl_xor_sync(~0u, ss, o);
            float inv = 1.0f / fmaxf(sqrtf(ss), 1e-12f);
            float2 ko = {mk.x * inv * k_scale[h * DHh + 2 * lane],
                         mk.y * inv * k_scale[h * DHh + 2 * lane + 1]};
            int bh = b * Hh + h;
            wr_hl(g_Kh, g_Kl, ((size_t)bh * PJ + m) * DHh, lane, ko);
            wr_hl16(g_Vh16, g_Vl16, ((size_t)bh * PJ + m) * DHh, lane, mv);
        }
    }
}

// ---------------- dots = Q K^T (HMMA bf16 hi/lo, raw scores) ---------------
__global__ __launch_bounds__(128) void dots_hmma() {
    int bh = blockIdx.y;
    int x = blockIdx.x;
    int ib = 0;
#pragma unroll 1
    while (((ib + 1) * (ib + 4)) / 2 <= x) ib++;
    int jb = x - (ib * (ib + 3)) / 2;
    int i0 = ib * 64, j0 = jb * 64;
    __shared__ __align__(128) char sm[32768];
    uint32_t sb = smem_u32(sm);
    int t = threadIdx.x, lane = t & 31, w = t >> 5;
    const __nv_bfloat16* Qh = g_Qh + ((size_t)bh * Nn + i0) * DHh;
    const __nv_bfloat16* Ql = g_Ql + ((size_t)bh * Nn + i0) * DHh;
    const __nv_bfloat16* Kh = g_Kh + ((size_t)bh * PJ + j0) * DHh;
    const __nv_bfloat16* Kl = g_Kl + ((size_t)bh * PJ + j0) * DHh;
#pragma unroll
    for (int i = 0; i < 16; i++) {
        int idx = t + i * 128;
        int tile = idx >> 9;
        int ci = idx & 511, r = ci >> 3, c = ci & 7;
        const __nv_bfloat16* src = (tile == 0) ? Qh : (tile == 1) ? Ql
                                 : (tile == 2) ? Kh : Kl;
        cp_async16(sb + tile * 8192 + r * 128 + ((c ^ (r & 7)) << 4),
                   src + (size_t)r * DHh + c * 8);
    }
    cp_commit(); cp_wait0();
    __syncthreads();
    int m0 = w * 16;
    float acc[8][4] = {};
    int a_r = m0 + ((lane >> 3) & 1) * 8 + (lane & 7);
    int a_c2 = lane >> 4;
    int b_r = (lane & 7) + ((lane >> 4) & 1) * 8;
    int b_c2 = (lane >> 3) & 1;
    uint32_t aH = sb, aL = sb + 8192, bH = sb + 16384, bL = sb + 24576;
#pragma unroll
    for (int pass = 0; pass < 3; pass++) {
        uint32_t at = (pass == 2) ? aL : aH;
        uint32_t bt = (pass == 1) ? bL : bH;
#pragma unroll
        for (int kk = 0; kk < 4; kk++) {
            uint32_t fA[4];
            int c = kk * 2 + a_c2;
            ldsm_x4(fA, at + a_r * 128 + ((c ^ (a_r & 7)) << 4));
#pragma unroll
            for (int ng = 0; ng < 4; ng++) {
                uint32_t fB[4];
                int n = ng * 16 + b_r;
                int cb = kk * 2 + b_c2;
                ldsm_x4(fB, bt + n * 128 + ((cb ^ (n & 7)) << 4));
                mma16816(acc[ng * 2], fA, fB);
                mma16816(acc[ng * 2 + 1], fA, fB + 2);
            }
        }
    }
    int row = i0 + m0 + (lane >> 2);
    int cb = (lane & 3) * 2;
    float* D = g_dots + (size_t)bh * Nn * NJ;
#pragma unroll
    for (int nb = 0; nb < 8; nb++) {
        int col = j0 + nb * 8 + cb;
        if (col < NJ) {
            float2 v0 = {acc[nb][0], acc[nb][1]};
            float2 v1 = {acc[nb][2], acc[nb][3]};
            *(float2*)&D[(size_t)row * NJ + col] = v0;
            *(float2*)&D[(size_t)(row + 8) * NJ + col] = v1;
        }
    }
}

// --- fused: pre-mix -> softmax -> post-mix(inv folded) -> fp16 P -----------
__global__ __launch_bounds__(512) void softmax_kernel(const float* __restrict__ W_pre,
                                                      const float* __restrict__ W_post) {
    extern __shared__ float smemf[];
    float* sD = smemf;                 // 16 * NJ
    float* sWpre = sD + 16 * NJ;       // 256
    float* sWpost = sWpre + 256;       // 256
    float* sInv = sWpost + 256;        // 16
    int t = threadIdx.x;
    int i = blockIdx.x, b = blockIdx.y;
    if (t < 256) { sWpre[t] = W_pre[t] * QK_SCALE; sWpost[t] = W_post[t]; }
    int jcount = i + 17;
    int g = t >> 5, lane = t & 31;
    int jsel = (t & 255) * 2;          // 0..510
    int g8 = (t >> 8) * 8;             // 0 or 8

    {
        const float* src = &g_dots[((size_t)(b * Hh + g) * Nn + i) * NJ];
        float* dst = sD + g * NJ;
        for (int j = lane * 4; j < jcount; j += 128)
            *(float4*)&dst[j] = *(const float4*)&src[j];
    }
    __syncthreads();

    {
        int nIter = (jcount + 511) / 512;
        for (int it = 0; it < nIter; it++) {
            int j = it * 512 + jsel;
            bool act = (j < jcount);
            float2 col[16];
            if (act) {
#pragma unroll
                for (int h = 0; h < 16; h++) col[h] = *(const float2*)&sD[h * NJ + j];
            }
            __syncthreads();
            if (act) {
#pragma unroll
                for (int gg = 0; gg < 8; gg++) {
                    int gd = g8 + gg;
                    float ax = 0.f, ay = 0.f;
#pragma unroll
                    for (int h = 0; h < 16; h++) {
                        float wv = sWpre[gd * 16 + h];
                        ax += wv * col[h].x; ay += wv * col[h].y;
                    }
                    float2 o2 = {ax, ay};
                    *(float2*)&sD[gd * NJ + j] = o2;
                }
            }
            __syncthreads();
        }
    }

    {
        float* row = sD + g * NJ;
        float m = -FLT_MAX;
        for (int j = lane; j < jcount; j += 32) m = fmaxf(m, row[j]);
#pragma unroll
        for (int o = 16; o > 0; o >>= 1) m = fmaxf(m, __shfl_xor_sync(~0u, m, o));
        float l = 0.f;
        for (int j = lane; j < jcount; j += 32) {
            float e = __expf(row[j] - m); row[j] = e; l += e;
        }
#pragma unroll
        for (int o = 16; o > 0; o >>= 1) l += __shfl_xor_sync(~0u, l, o);
        if (lane == 0) sInv[g] = 1.f / l;
    }
    __syncthreads();

    int jendP = (i & ~127) + 192;
    size_t pbase = ((size_t)(b * Hh) * Nn + i) * PJ;
    float wp[16];
#pragma unroll 1
    for (int gg = 0; gg < 8; gg++) {
        int gd = g8 + gg;
#pragma unroll
        for (int h = 0; h < 16; h++) wp[h] = sWpost[gd * 16 + h] * sInv[h];
        __half* ph = (__half*)&g_P16[pbase + (size_t)gd * Nn * PJ];
        for (int j = jsel; j < jendP; j += 512) {
            float ax = 0.f, ay = 0.f;
            if (j < jcount) {
#pragma unroll
                for (int h = 0; h < 16; h++) {
                    float2 d2 = *(const float2*)&sD[h * NJ + j];
                    ax += wp[h] * d2.x; ay += wp[h] * d2.y;
                }
                if (j + 1 >= jcount) ay = 0.f;
            }
            __half2 hh; hh.x = __float2half(ax); hh.y = __float2half(ay);
            *(__half2*)&ph[j] = hh;
        }
    }
}

// ------- O_g = P_g @ V_g (fp16), 128-row i-tiles, 8 warps ------------------
__global__ __launch_bounds__(256) void av_hmma() {
    int bh = blockIdx.y;
    int i0 = blockIdx.x * 128;
    int ntiles = (i0 >> 6) + 3;
    extern __shared__ __align__(128) char sm[];   // 2 x 32768
    uint32_t sb = smem_u32(sm);
    int t = threadIdx.x, lane = t & 31, w = t >> 5;
    const __half* P = g_P16 + ((size_t)bh * Nn + i0) * PJ;
    const __half* Vh = g_Vh16 + (size_t)bh * PJ * DHh;
    const __half* Vl = g_Vl16 + (size_t)bh * PJ * DHh;

    auto issue = [&](int jt) {
        uint32_t st = sb + (uint32_t)(jt & 1) * 32768u;
#pragma unroll
        for (int i = 0; i < 8; i++) {
            int idx = t + i * 256;
            const __half* g;
            uint32_t soff;
            if (idx < 1024) {
                int r = idx >> 3, c = idx & 7;
                g = P + (size_t)r * PJ + jt * 64 + c * 8;
                soff = (uint32_t)(r * 128 + ((c ^ (r & 7)) << 4));
            } else if (idx < 1536) {
                int ci = idx - 1024, r = ci >> 3, c = ci & 7;
                g = Vh + (size_t)(jt * 64 + r) * DHh + c * 8;
                soff = 16384u + (uint32_t)(r * 128 + ((c ^ (r & 7)) << 4));
            } else {
                int ci = idx - 1536, r = ci >> 3, c = ci & 7;
                g = Vl + (size_t)(jt * 64 + r) * DHh + c * 8;
                soff = 24576u + (uint32_t)(r * 128 + ((c ^ (r & 7)) << 4));
            }
            cp_async16(st + soff, g);
        }
        cp_commit();
    };

    issue(0);
    float acc[8][4] = {};
    int m0 = w * 16;
    int a_r = m0 + ((lane >> 3) & 1) * 8 + (lane & 7);
    int a_c2 = lane >> 4;
    int v_j = (lane & 7) + ((lane >> 3) & 1) * 8;
    int v_c2 = lane >> 4;
    for (int jt = 0; jt < ntiles; jt++) {
        if (jt + 1 < ntiles) { issue(jt + 1); cp_wait1(); } else cp_wait0();
        __syncthreads();
        uint32_t st = sb + (uint32_t)(jt & 1) * 32768u;
        uint32_t pA = st, vH = st + 16384, vL = st + 24576;
#pragma unroll
        for (int kk = 0; kk < 4; kk++) {
            uint32_t fA[4];
            int c = kk * 2 + a_c2;
            ldsm_x4(fA, pA + a_r * 128 + ((c ^ (a_r & 7)) << 4));
#pragma unroll
            for (int dg = 0; dg < 4; dg++) {
                uint32_t fVh[4], fVl[4];
                int jr = kk * 16 + v_j;
                int cv = dg * 2 + v_c2;
                ldsm_x4_t(fVh, vH + jr * 128 + ((cv ^ (jr & 7)) << 4));
                ldsm_x4_t(fVl, vL + jr * 128 + ((cv ^ (jr & 7)) << 4));
                mma16816h(acc[dg * 2],     fA, fVh);
                mma16816h(acc[dg * 2 + 1], fA, fVh + 2);
                mma16816h(acc[dg * 2],     fA, fVl);
                mma16816h(acc[dg * 2 + 1], fA, fVl + 2);
            }
        }
        __syncthreads();
    }
    float* O = g_Ohd + ((size_t)bh * Nn + i0) * DHh;
    int row = m0 + (lane >> 2), cb = (lane & 3) * 2;
#pragma unroll
    for (int db = 0; db < 8; db++) {
        float2 v0 = {acc[db][0], acc[db][1]};
        float2 v1 = {acc[db][2], acc[db][3]};
        *(float2*)&O[(size_t)row * DHh + db * 8 + cb] = v0;
        *(float2*)&O[(size_t)(row + 8) * DHh + db * 8 + cb] = v1;
    }
}

// ------- gates only (post-mix already applied) -> fp16 ---------------------
__global__ __launch_bounds__(128) void mix_gate(const float* __restrict__ b_h,
                                                const float* __restrict__ b_v) {
    int rowid = blockIdx.x;             // 0..4095
    int b = rowid >> 10, n = rowid & 1023;
    int t = threadIdx.x;
#pragma unroll
    for (int k = 0; k < 8; k++) {
        int idx = t + k * 128; int g = idx >> 6, d = idx & 63;
        float a = g_Ohd[((size_t)(b * Hh + g) * Nn + n) * DHh + d];
        float hg = 1.f / (1.f + __expf(-(g_hgraw[(size_t)rowid * 16 + g] + b_h[g])));
        float vg = 1.f / (1.f + __expf(-(g_vgraw[(size_t)rowid * 1024 + idx] + b_v[idx])));
        g_of[(size_t)rowid * 1024 + idx] = __float2half(a * hg * vg);
    }
}

// ---------------------------------------------------------------------------
extern "C" void kernel_launch(void* const* d_in, const int* in_sizes, int n_in,
                              void* d_out, int out_size) {
    const float* x       = (const float*)d_in[0];
    const float* freqs   = (const float*)d_in[1];
    const float* Wq      = (const float*)d_in[2];
    const float* Wk      = (const float*)d_in[3];
    const float* Wv      = (const float*)d_in[4];
    const float* q_scale = (const float*)d_in[5];
    const float* k_scale = (const float*)d_in[6];
    const float* mem_k   = (const float*)d_in[7];
    const float* mem_v   = (const float*)d_in[8];
    const float* W_pre   = (const float*)d_in[9];
    const float* W_post  = (const float*)d_in[10];
    const float* W_hgate = (const float*)d_in[11];
    const float* b_hgate = (const float*)d_in[12];
    const float* W_vgate = (const float*)d_in[13];
    const float* b_vgate = (const float*)d_in[14];
    const float* Wo      = (const float*)d_in[15];
    float* out = (float*)d_out;

    float *Qraw, *Kraw, *Vraw, *vgraw;
    __nv_bfloat16 *Ahi, *Alo;
    __half *xf, *of;
    cudaGetSymbolAddress((void**)&Qraw, g_Qraw);
    cudaGetSymbolAddress((void**)&Kraw, g_Kraw);
    cudaGetSymbolAddress((void**)&Vraw, g_Vraw);
    cudaGetSymbolAddress((void**)&vgraw, g_vgraw);
    cudaGetSymbolAddress((void**)&Ahi, g_Ahi);
    cudaGetSymbolAddress((void**)&Alo, g_Alo);
    cudaGetSymbolAddress((void**)&xf, g_xf);
    cudaGetSymbolAddress((void**)&of, g_of);

    conv_x<<<ROWS * DIMm / 1024, 256>>>(x);
    conv_w_t<<<dim3(32, 32, 5), 256>>>(Wq, Wk, Wv, W_vgate, Wo);
    hg_t<<<64, 256>>>(W_hgate);

    cudaFuncSetAttribute(mma_gemm_bf, cudaFuncAttributeMaxDynamicSharedMemorySize, 131072);
    cudaFuncSetAttribute(mma_gemm_f16, cudaFuncAttributeMaxDynamicSharedMemorySize, 98304);
    mma_gemm_bf<<<dim3(DIMm / 128, ROWS / 128, 2), 256, 131072>>>(Ahi, Alo, Qraw, Kraw);
    mma_gemm_f16<<<dim3(DIMm / 128, ROWS / 128, 2), 256, 98304>>>(xf, 0, Vraw, vgraw);
    hgate_warp<<<ROWS / 4, 128>>>(x);

    int warps = Bb * Nn * Hh + Bb * Hh * Mm;
    prep_kernel<<<(warps + 7) / 8, 256>>>(freqs, q_scale, k_scale, mem_k, mem_v);

    dots_hmma<<<dim3(152, 64), 128>>>();

    size_t smem_bytes = (16 * NJ + 512 + 16) * sizeof(float);
    cudaFuncSetAttribute(softmax_kernel, cudaFuncAttributeMaxDynamicSharedMemorySize,
                         (int)smem_bytes);
    softmax_kernel<<<dim3(Nn, Bb), 512, smem_bytes>>>(W_pre, W_post);

    cudaFuncSetAttribute(av_hmma, cudaFuncAttributeMaxDynamicSharedMemorySize, 65536);
    av_hmma<<<dim3(Nn / 128, 64), 256, 65536>>>();

    mix_gate<<<ROWS, 128>>>(b_hgate, b_vgate);

    mma_gemm_f16<<<dim3(DIMm / 128, ROWS / 128, 1), 256, 98304>>>(of, 2, out, out);
}